// round 1
// baseline (speedup 1.0000x reference)
#include <cuda_runtime.h>

// Problem: out[b,c,h,w] = (Re + Im)( FFT4D(x) )[b,c,h,w] / 2^26
// x: [16, 64, 256, 256] float32.  The spectral-conv weights are dead code.
//
// Scratch: half-spectrum Y[w'][b][c][h], w' in [0,128], complex64.
// 129 * 1024 * 256 = 33,816,576 float2 (~270 MB) device global.
__device__ float2 g_Y[33816576];

#define INV_N (1.0f / 67108864.0f)

__device__ __forceinline__ float2 cmul(float2 a, float2 b) {
    return make_float2(a.x * b.x - a.y * b.y, a.x * b.y + a.y * b.x);
}

__device__ __forceinline__ void fill_tw(float2* tw, int tid, int nthreads) {
    // tw[j] = exp(-2*pi*i * j / 256), j in [0,128)
    for (int i = tid; i < 128; i += nthreads) {
        float s, c;
        sincospif(-(float)i * (1.0f / 128.0f), &s, &c);
        tw[i] = make_float2(c, s);
    }
}

// F(p) = p + (p>>3): bank-conflict-reducing swizzle for 256-long rows
#define FSW(p) ((p) + ((p) >> 3))

// ---------------------------------------------------------------------------
// P1: real 256-pt FFT along W. Block = (bc, h-tile of 16 rows).
// Stores transposed: Y[w'][bc][h], w' in [0,128].
// ---------------------------------------------------------------------------
__global__ void __launch_bounds__(256) p1_kernel(const float* __restrict__ x) {
    __shared__ float2 s[16][289];   // 256-pt rows with swizzle headroom
    __shared__ float2 tw[128];
    int tid = threadIdx.x;
    int bc  = blockIdx.x;           // 0..1023
    int h0  = blockIdx.y << 4;      // 0,16,...,240

    fill_tw(tw, tid, 256);

    const float* xr = x + ((size_t)bc * 256 + h0) * 256;
    for (int idx = tid; idx < 16 * 256; idx += 256) {
        int hh = idx >> 8, w = idx & 255;
        float v = xr[hh * 256 + w];
        int p = __brev((unsigned)w) >> 24;          // bit-reverse 8 bits
        s[hh][FSW(p)] = make_float2(v, 0.0f);
    }
    __syncthreads();

    // in-place DIT, 8 stages, 16 rows x 128 butterflies = 2048 per stage
    for (int st = 0; st < 8; st++) {
        int half = 1 << st;
        for (int it = tid; it < 2048; it += 256) {
            int row = it >> 7;
            int j   = it & 127;
            int k   = j & (half - 1);
            int i0  = ((j >> st) << (st + 1)) + k;
            int i1  = i0 + half;
            int f0 = FSW(i0), f1 = FSW(i1);
            float2 a = s[row][f0];
            float2 b = s[row][f1];
            float2 t = cmul(tw[k << (7 - st)], b);
            s[row][f0] = make_float2(a.x + t.x, a.y + t.y);
            s[row][f1] = make_float2(a.x - t.x, a.y - t.y);
        }
        __syncthreads();
    }

    // store w' in [0,128]; 16 consecutive h per w' -> 128B chunks
    for (int idx = tid; idx < 129 * 16; idx += 256) {
        int w  = idx >> 4;
        int hh = idx & 15;
        g_Y[((size_t)w * 1024 + bc) * 256 + h0 + hh] = s[hh][FSW(w)];
    }
}

// ---------------------------------------------------------------------------
// P2: complex 256-pt FFT along H (contiguous rows). 2 rows per 256-thr block.
// Rows indexed by (w'*1024 + bc), 132096 total.
// ---------------------------------------------------------------------------
__global__ void __launch_bounds__(256) p2_kernel() {
    __shared__ float2 s[2][289];
    __shared__ float2 tw[128];
    int tid = threadIdx.x;
    size_t r0 = (size_t)blockIdx.x * 2;

    fill_tw(tw, tid, 256);

    for (int idx = tid; idx < 512; idx += 256) {
        int row = idx >> 8, h = idx & 255;
        float2 v = g_Y[(r0 + row) * 256 + h];
        int p = __brev((unsigned)h) >> 24;
        s[row][FSW(p)] = v;
    }
    __syncthreads();

    int row = tid >> 7;
    int j   = tid & 127;
    for (int st = 0; st < 8; st++) {
        int half = 1 << st;
        int k  = j & (half - 1);
        int i0 = ((j >> st) << (st + 1)) + k;
        int i1 = i0 + half;
        int f0 = FSW(i0), f1 = FSW(i1);
        float2 a = s[row][f0];
        float2 b = s[row][f1];
        float2 t = cmul(tw[k << (7 - st)], b);
        s[row][f0] = make_float2(a.x + t.x, a.y + t.y);
        s[row][f1] = make_float2(a.x - t.x, a.y - t.y);
        __syncthreads();
    }

    for (int idx = tid; idx < 512; idx += 256) {
        int rw = idx >> 8, h = idx & 255;
        g_Y[(r0 + rw) * 256 + h] = s[rw][FSW(h)];
    }
}

// ---------------------------------------------------------------------------
// P3: fused 64-pt C-FFT + 16-pt B-FFT. Block = (w', h-chunk of 4).
// Tile [b=16][c=64][t=4] complex in smem (32 KB), bit-reversed load, DIT.
// ---------------------------------------------------------------------------
__global__ void __launch_bounds__(512) p3_kernel() {
    __shared__ float2 s[16 * 64 * 4];
    __shared__ float2 tw[128];
    int tid = threadIdx.x;
    int w  = blockIdx.x;          // 0..128
    int h0 = blockIdx.y << 2;     // 0,4,...,252

    fill_tw(tw, tid, 512);

    // load with per-axis bit-reversed placement (separable)
    for (int idx = tid; idx < 4096; idx += 512) {
        int bc = idx >> 2, t = idx & 3;
        int b = bc >> 6, c = bc & 63;
        float2 v = g_Y[((size_t)w * 1024 + bc) * 256 + h0 + t];
        int bs = __brev((unsigned)b) >> 28;   // 4-bit reverse
        int cs = __brev((unsigned)c) >> 26;   // 6-bit reverse
        s[(((bs << 6) | cs) << 2) | t] = v;
    }
    __syncthreads();

    // C-axis FFT: n=64, 6 stages, 16*32*4 = 2048 butterflies/stage
    for (int st = 0; st < 6; st++) {
        int half = 1 << st;
        for (int it = tid; it < 2048; it += 512) {
            int t = it & 3;
            int j = (it >> 2) & 31;
            int b = it >> 7;
            int k = j & (half - 1);
            int c0 = ((j >> st) << (st + 1)) + k;
            int i0 = (((b << 6) | c0) << 2) | t;
            int i1 = i0 + (half << 2);
            float2 a = s[i0];
            float2 bb = s[i1];
            float2 tt = cmul(tw[k << (7 - st)], bb);
            s[i0] = make_float2(a.x + tt.x, a.y + tt.y);
            s[i1] = make_float2(a.x - tt.x, a.y - tt.y);
        }
        __syncthreads();
    }

    // B-axis FFT: n=16, 4 stages, 8*64*4 = 2048 butterflies/stage
    for (int st = 0; st < 4; st++) {
        int half = 1 << st;
        for (int it = tid; it < 2048; it += 512) {
            int t = it & 3;
            int c = (it >> 2) & 63;
            int j = it >> 8;
            int k = j & (half - 1);
            int b0 = ((j >> st) << (st + 1)) + k;
            int i0 = (((b0 << 6) | c) << 2) | t;
            int i1 = i0 + (half << 8);   // half * 64 * 4
            float2 a = s[i0];
            float2 bb = s[i1];
            float2 tt = cmul(tw[k << (7 - st)], bb);
            s[i0] = make_float2(a.x + tt.x, a.y + tt.y);
            s[i1] = make_float2(a.x - tt.x, a.y - tt.y);
        }
        __syncthreads();
    }

    for (int idx = tid; idx < 4096; idx += 512) {
        int bc = idx >> 2, t = idx & 3;
        g_Y[((size_t)w * 1024 + bc) * 256 + h0 + t] = s[idx];
    }
}

// ---------------------------------------------------------------------------
// P4: output. Direct half: out[bc][h][w] = (Re+Im)/N for w in [0,128].
// Mirror half via Hermitian symmetry:
//   out[bcm][hm][256-w'] = (Re-Im)/N for w' in [1,127],
//   bcm = mirror(b,c), hm = (256-h)&255.
// 32x32 (w' x h) smem tile, all global accesses coalesced.
// ---------------------------------------------------------------------------
__global__ void __launch_bounds__(256) p4_kernel(float* __restrict__ out) {
    __shared__ float2 ts[32][33];
    int tid  = threadIdx.x;
    int lane = tid & 31;
    int wrp  = tid >> 5;
    int bc = blockIdx.x;
    int w0 = blockIdx.y << 5;   // 0,32,64,96,128
    int h0 = blockIdx.z << 5;   // 0..224

    for (int r = wrp; r < 32; r += 8) {
        int w = w0 + r;
        if (w <= 128)
            ts[r][lane] = g_Y[((size_t)w * 1024 + bc) * 256 + h0 + lane];
    }
    __syncthreads();

    int b = bc >> 6, c = bc & 63;
    int bcm = (((16 - b) & 15) << 6) | ((64 - c) & 63);

    int wv = w0 + lane;   // source w'
    for (int j = 0; j < 4; j++) {
        int hh = wrp + (j << 3);
        int h  = h0 + hh;
        float2 v = ts[lane][hh];
        if (wv <= 128)
            out[((size_t)bc * 256 + h) * 256 + wv] = (v.x + v.y) * INV_N;
        if (wv >= 1 && wv <= 127) {
            int hm = (256 - h) & 255;
            out[((size_t)bcm * 256 + hm) * 256 + (256 - wv)] = (v.x - v.y) * INV_N;
        }
    }
}

// ---------------------------------------------------------------------------
extern "C" void kernel_launch(void* const* d_in, const int* in_sizes, int n_in,
                              void* d_out, int out_size) {
    (void)in_sizes; (void)n_in; (void)out_size;
    const float* x = (const float*)d_in[0];   // [16,64,256,256] float32
    float* out = (float*)d_out;               // [16,64,256,256] float32

    p1_kernel<<<dim3(1024, 16), 256>>>(x);
    p2_kernel<<<66048, 256>>>();
    p3_kernel<<<dim3(129, 64), 512>>>();
    p4_kernel<<<dim3(1024, 5, 8), 256>>>(out);
}

// round 3
// speedup vs baseline: 2.2464x; 2.2464x over previous
#include <cuda_runtime.h>

// out[b,c,h,w] = (Re + Im)( FFT4D(x) ) / 2^26 ; x: [16,64,256,256] f32.
// Scratch: half-spectrum Y[w'][bc][h], w' in [0,128], complex64 (~270MB).
// After P2, the h axis is stored in bit-reversed (DIF) order.
// After P3, the bc axis is stored as (p,q) with true (b,c) = (brev4(p), brev6(q)).
// P4 compensates both with __brev.
__device__ float2 g_Y[33816576];

#define INV_N (1.0f / 67108864.0f)

__device__ __forceinline__ float2 cmul(float2 a, float2 b) {
    return make_float2(a.x*b.x - a.y*b.y, a.x*b.y + a.y*b.x);
}
__device__ __forceinline__ float2 cadd(float2 a, float2 b) { return make_float2(a.x+b.x, a.y+b.y); }
__device__ __forceinline__ float2 csub(float2 a, float2 b) { return make_float2(a.x-b.x, a.y-b.y); }
// exp(-i*pi*e*sc)
__device__ __forceinline__ float2 Wang(float e, float sc) {
    float2 w; sincospif(-e*sc, &w.y, &w.x); return w;
}

// ---------------------------------------------------------------------------
// Warp-resident 256-pt DIF FFT. Input: z[i] = x[lane + 32*i] (natural order).
// Output: position n = lane + 32*i holds X[bitrev8(n)].
// ---------------------------------------------------------------------------
__device__ __forceinline__ void fft256_warp(float2 z[8], int lane) {
    const float sc = 1.0f / 128.0f;   // W256^e -> angle = -pi*e/128
    // h = 128: pairs (i, i+4), e = lane + 32*i
#pragma unroll
    for (int i = 0; i < 4; i++) {
        float2 a = z[i], b = z[i+4];
        z[i]   = cadd(a, b);
        z[i+4] = cmul(Wang((float)(lane + 32*i), sc), csub(a, b));
    }
    // h = 64: pairs (0,2)(1,3)(4,6)(5,7), e = 2*lane (+64 for odd i)
    {
        float2 w0 = Wang((float)(2*lane), sc);
        float2 w1 = Wang((float)(2*lane + 64), sc);
        float2 a, b;
        a = z[0]; b = z[2]; z[0] = cadd(a,b); z[2] = cmul(w0, csub(a,b));
        a = z[1]; b = z[3]; z[1] = cadd(a,b); z[3] = cmul(w1, csub(a,b));
        a = z[4]; b = z[6]; z[4] = cadd(a,b); z[6] = cmul(w0, csub(a,b));
        a = z[5]; b = z[7]; z[5] = cadd(a,b); z[7] = cmul(w1, csub(a,b));
    }
    // h = 32: pairs (i, i+1) for even i, e = 4*lane
    {
        float2 w = Wang((float)(4*lane), sc);
#pragma unroll
        for (int i = 0; i < 8; i += 2) {
            float2 a = z[i], b = z[i+1];
            z[i]   = cadd(a, b);
            z[i+1] = cmul(w, csub(a, b));
        }
    }
    // cross-lane stages h = m = 16,8,4,2,1 ; e = (lane & (m-1)) * (128/m)
#pragma unroll
    for (int m = 16; m >= 1; m >>= 1) {
        float2 w = Wang((float)((lane & (m-1)) * (128/m)), sc);
        bool hi = (lane & m) != 0;
#pragma unroll
        for (int i = 0; i < 8; i++) {
            float2 o;
            o.x = __shfl_xor_sync(0xffffffffu, z[i].x, m);
            o.y = __shfl_xor_sync(0xffffffffu, z[i].y, m);
            if (hi) z[i] = cmul(w, csub(o, z[i]));   // (a - b) * w
            else    z[i] = cadd(z[i], o);            // a + b
        }
    }
}

// F(p) = p + (p>>3): bank-spreading swizzle for 256-long smem rows
#define FSW(p) ((p) + ((p) >> 3))

// ---------------------------------------------------------------------------
// P1: real 256-pt FFT along W, two-for-one (h-row pairs packed re/im).
// Block: bc fixed, 16 h rows = 8 warp-FFTs. Stores Y[w'][bc][h], w' in [0,128].
// ---------------------------------------------------------------------------
__global__ void __launch_bounds__(256) p1_kernel(const float* __restrict__ x) {
    __shared__ float2 S[8][289];
    int tid  = threadIdx.x;
    int lane = tid & 31, wp = tid >> 5;
    int bc = blockIdx.x;
    int h0 = blockIdx.y << 4;

    const float* r0 = x + ((size_t)bc * 256 + h0 + 2*wp) * 256;
    const float* r1 = r0 + 256;
    float2 z[8];
#pragma unroll
    for (int i = 0; i < 8; i++) {
        int n = lane + 32*i;
        z[i] = make_float2(r0[n], r1[n]);
    }
    fft256_warp(z, lane);
#pragma unroll
    for (int i = 0; i < 8; i++) {
        int n = lane + 32*i;
        int k = __brev((unsigned)n) >> 24;      // natural frequency index
        S[wp][FSW(k)] = z[i];
    }
    __syncthreads();

    // Hermitian unpack of the packed pair + transposed store.
    for (int idx = tid; idx < 129 * 16; idx += 256) {
        int w  = idx >> 4;        // w' 0..128
        int hh = idx & 15;
        int pr = hh >> 1, od = hh & 1;
        float2 Z  = S[pr][FSW(w)];
        float2 Zm = S[pr][FSW((256 - w) & 255)];
        float2 X;
        if (!od) X = make_float2(0.5f*(Z.x + Zm.x), 0.5f*(Z.y - Zm.y));
        else     X = make_float2(0.5f*(Z.y + Zm.y), 0.5f*(Zm.x - Z.x));
        g_Y[((size_t)w * 1024 + bc) * 256 + h0 + hh] = X;
    }
}

// ---------------------------------------------------------------------------
// P2: complex 256-pt FFT along H. One row per warp, 8 rows per block.
// No smem, no barriers. Output stored in bit-reversed h order.
// ---------------------------------------------------------------------------
__global__ void __launch_bounds__(256) p2_kernel() {
    int lane = threadIdx.x & 31, wp = threadIdx.x >> 5;
    size_t row = (size_t)blockIdx.x * 8 + wp;
    float2* g = g_Y + row * 256;
    float2 z[8];
#pragma unroll
    for (int i = 0; i < 8; i++) z[i] = g[lane + 32*i];
    fft256_warp(z, lane);
#pragma unroll
    for (int i = 0; i < 8; i++) g[lane + 32*i] = z[i];
}

// ---------------------------------------------------------------------------
// P3: fused 16-pt B-FFT (in registers, from global) + 64-pt C-FFT (warp
// shuffles, via one smem transpose). Block: w' fixed, 4 stored-h positions.
// Output bc axis scrambled: stored (p,q) -> true (brev4(p), brev6(q)).
// ---------------------------------------------------------------------------
__global__ void __launch_bounds__(256) p3_kernel() {
    __shared__ __align__(16) float2 S[16 * 256];   // [p][c*4 + t], 32KB
    int tid = threadIdx.x;
    int wq = blockIdx.x;          // 0..128
    int h0 = blockIdx.y << 2;     // stored-h base, 0..252

    // Phase A: 16-pt DIF over b, fully in registers.
    {
        int c = tid >> 2, t = tid & 3;
        float2 r[16];
#pragma unroll
        for (int b = 0; b < 16; b++)
            r[b] = g_Y[((size_t)wq * 1024 + b * 64 + c) * 256 + h0 + t];
        float2 t16[8];
#pragma unroll
        for (int e = 0; e < 8; e++) t16[e] = Wang((float)e, 0.125f);
#pragma unroll
        for (int h = 8; h >= 1; h >>= 1) {
#pragma unroll
            for (int base = 0; base < 16; base += 2*h) {
#pragma unroll
                for (int j = 0; j < h; j++) {
                    float2 a = r[base+j], b = r[base+j+h];
                    r[base+j]   = cadd(a, b);
                    r[base+j+h] = cmul(t16[j * (8/h)], csub(a, b));
                }
            }
        }
#pragma unroll
        for (int p = 0; p < 16; p++) S[p * 256 + c * 4 + t] = r[p];
    }
    __syncthreads();

    // Phase B: 64-pt DIF over c via warp shuffles, 4 t-values per thread.
    int lane = tid & 31, wp = tid >> 5;
    const float sc = 1.0f / 32.0f;   // W64^e
#pragma unroll
    for (int pp = 0; pp < 2; pp++) {
        int p = wp + 8 * pp;
        const float4* Sp = (const float4*)(S + p * 256);
        float2 z0[4], z1[4];
        float4 v;
        v = Sp[lane*2 + 0];        z0[0] = make_float2(v.x, v.y); z0[1] = make_float2(v.z, v.w);
        v = Sp[lane*2 + 1];        z0[2] = make_float2(v.x, v.y); z0[3] = make_float2(v.z, v.w);
        v = Sp[(lane+32)*2 + 0];   z1[0] = make_float2(v.x, v.y); z1[1] = make_float2(v.z, v.w);
        v = Sp[(lane+32)*2 + 1];   z1[2] = make_float2(v.x, v.y); z1[3] = make_float2(v.z, v.w);

        // h = 32: register pair (z0, z1), e = lane
        {
            float2 w = Wang((float)lane, sc);
#pragma unroll
            for (int t = 0; t < 4; t++) {
                float2 a = z0[t], b = z1[t];
                z0[t] = cadd(a, b);
                z1[t] = cmul(w, csub(a, b));
            }
        }
        // cross stages m = 16..1, e = (lane & (m-1)) * (32/m)
#pragma unroll
        for (int m = 16; m >= 1; m >>= 1) {
            float2 w = Wang((float)((lane & (m-1)) * (32/m)), sc);
            bool hi = (lane & m) != 0;
#pragma unroll
            for (int t = 0; t < 4; t++) {
                float2 o;
                o.x = __shfl_xor_sync(0xffffffffu, z0[t].x, m);
                o.y = __shfl_xor_sync(0xffffffffu, z0[t].y, m);
                z0[t] = hi ? cmul(w, csub(o, z0[t])) : cadd(z0[t], o);
                o.x = __shfl_xor_sync(0xffffffffu, z1[t].x, m);
                o.y = __shfl_xor_sync(0xffffffffu, z1[t].y, m);
                z1[t] = hi ? cmul(w, csub(o, z1[t])) : cadd(z1[t], o);
            }
        }
        // store: 32B vectorized (4 consecutive stored-h float2 per row)
        float2* d0 = g_Y + ((size_t)wq * 1024 + p * 64 + lane) * 256 + h0;
        float2* d1 = g_Y + ((size_t)wq * 1024 + p * 64 + lane + 32) * 256 + h0;
        ((float4*)d0)[0] = make_float4(z0[0].x, z0[0].y, z0[1].x, z0[1].y);
        ((float4*)d0)[1] = make_float4(z0[2].x, z0[2].y, z0[3].x, z0[3].y);
        ((float4*)d1)[0] = make_float4(z1[0].x, z1[0].y, z1[1].x, z1[1].y);
        ((float4*)d1)[1] = make_float4(z1[2].x, z1[2].y, z1[3].x, z1[3].y);
    }
}

// ---------------------------------------------------------------------------
// P4: output with Hermitian mirror. Index compensation: true h = brev8(stored),
// true (b,c) = (brev4(ps), brev6(qs)). Writes stay w-contiguous (coalesced).
// ---------------------------------------------------------------------------
__global__ void __launch_bounds__(256) p4_kernel(float* __restrict__ out) {
    __shared__ float2 ts[32][33];
    int tid  = threadIdx.x;
    int lane = tid & 31;
    int wrp  = tid >> 5;
    int bcs = blockIdx.x;          // stored bc
    int w0 = blockIdx.y << 5;      // 0,32,64,96,128
    int h0 = blockIdx.z << 5;      // stored h base

    for (int r = wrp; r < 32; r += 8) {
        int wq = w0 + r;
        if (wq <= 128)
            ts[r][lane] = g_Y[((size_t)wq * 1024 + bcs) * 256 + h0 + lane];
    }
    __syncthreads();

    int bs = bcs >> 6, cs = bcs & 63;
    int b = __brev((unsigned)bs) >> 28;    // true b
    int c = __brev((unsigned)cs) >> 26;    // true c
    int bc  = (b << 6) | c;
    int bcm = (((16 - b) & 15) << 6) | ((64 - c) & 63);

    int wv = w0 + lane;
    for (int j = 0; j < 4; j++) {
        int hh = wrp + (j << 3);
        int hs = h0 + hh;                          // stored h
        int h  = __brev((unsigned)hs) >> 24;       // true h
        float2 v = ts[lane][hh];
        if (wv <= 128)
            out[((size_t)bc * 256 + h) * 256 + wv] = (v.x + v.y) * INV_N;
        if (wv >= 1 && wv <= 127) {
            int hm = (256 - h) & 255;
            out[((size_t)bcm * 256 + hm) * 256 + (256 - wv)] = (v.x - v.y) * INV_N;
        }
    }
}

// ---------------------------------------------------------------------------
extern "C" void kernel_launch(void* const* d_in, const int* in_sizes, int n_in,
                              void* d_out, int out_size) {
    (void)in_sizes; (void)n_in; (void)out_size;
    const float* x = (const float*)d_in[0];
    float* out = (float*)d_out;

    p1_kernel<<<dim3(1024, 16), 256>>>(x);
    p2_kernel<<<16512, 256>>>();
    p3_kernel<<<dim3(129, 64), 256>>>();
    p4_kernel<<<dim3(1024, 5, 8), 256>>>(out);
}

// round 4
// speedup vs baseline: 2.4899x; 1.1084x over previous
#include <cuda_runtime.h>

// out[b,c,h,w] = (Re + Im)( FFT4D(x) ) / 2^26 ; x: [16,64,256,256] f32.
//
// Pipeline (scratch rows padded: W2 = 132 float2 per 129 used):
//  p1 : x -> A[bc][h][w']     (real 256-pt W-FFT, two-for-one, warp-private)
//  p2 : A -> B[hs][bc][w']    (256-pt H-FFT per w' column; hs = brev8(h))
//  p2e: same for w'=128 column
//  p3 : B -> out              (16-pt B-FFT + 64-pt C-FFT + Hermitian mirror
//                              output, fused; w' 0..127)
//  p3e: w'=128 plane -> out column w=128
#define W2 132
__device__ float2 g_A[34603008];   // 1024*256*132
__device__ float2 g_B[34603008];

#define INV_N (1.0f / 67108864.0f)

__device__ __forceinline__ float2 cmul(float2 a, float2 b) {
    return make_float2(a.x*b.x - a.y*b.y, a.x*b.y + a.y*b.x);
}
__device__ __forceinline__ float2 cadd(float2 a, float2 b) { return make_float2(a.x+b.x, a.y+b.y); }
__device__ __forceinline__ float2 csub(float2 a, float2 b) { return make_float2(a.x-b.x, a.y-b.y); }
__device__ __forceinline__ float2 Wang(float e, float sc) {   // exp(-i*pi*e*sc)
    float2 w; sincospif(-e*sc, &w.y, &w.x); return w;
}
__device__ __forceinline__ int brev4(int v) { return (int)(__brev((unsigned)v) >> 28); }
__device__ __forceinline__ int brev6(int v) { return (int)(__brev((unsigned)v) >> 26); }
__device__ __forceinline__ int brev8(int v) { return (int)(__brev((unsigned)v) >> 24); }

// ---------------------------------------------------------------------------
// Warp-resident 256-pt DIF FFT. Input z[i] = x[lane + 32*i] natural order.
// Output: position n = lane + 32*i holds X[brev8(n)].
// ---------------------------------------------------------------------------
__device__ __forceinline__ void fft256_warp(float2 z[8], int lane) {
    const float sc = 1.0f / 128.0f;
#pragma unroll
    for (int i = 0; i < 4; i++) {                       // h = 128
        float2 a = z[i], b = z[i+4];
        z[i]   = cadd(a, b);
        z[i+4] = cmul(Wang((float)(lane + 32*i), sc), csub(a, b));
    }
    {                                                   // h = 64
        float2 w0 = Wang((float)(2*lane), sc);
        float2 w1 = Wang((float)(2*lane + 64), sc);
        float2 a, b;
        a = z[0]; b = z[2]; z[0] = cadd(a,b); z[2] = cmul(w0, csub(a,b));
        a = z[1]; b = z[3]; z[1] = cadd(a,b); z[3] = cmul(w1, csub(a,b));
        a = z[4]; b = z[6]; z[4] = cadd(a,b); z[6] = cmul(w0, csub(a,b));
        a = z[5]; b = z[7]; z[5] = cadd(a,b); z[7] = cmul(w1, csub(a,b));
    }
    {                                                   // h = 32
        float2 w = Wang((float)(4*lane), sc);
#pragma unroll
        for (int i = 0; i < 8; i += 2) {
            float2 a = z[i], b = z[i+1];
            z[i]   = cadd(a, b);
            z[i+1] = cmul(w, csub(a, b));
        }
    }
#pragma unroll
    for (int m = 16; m >= 1; m >>= 1) {                 // cross-lane stages
        float2 w = Wang((float)((lane & (m-1)) * (128/m)), sc);
        bool hi = (lane & m) != 0;
#pragma unroll
        for (int i = 0; i < 8; i++) {
            float2 o;
            o.x = __shfl_xor_sync(0xffffffffu, z[i].x, m);
            o.y = __shfl_xor_sync(0xffffffffu, z[i].y, m);
            if (hi) z[i] = cmul(w, csub(o, z[i]));
            else    z[i] = cadd(z[i], o);
        }
    }
}

// 16-pt DIF: in/out in r[]; position p holds spectrum index brev4(p).
__device__ __forceinline__ void dif16(float2 r[16], const float2 t16[8]) {
#pragma unroll
    for (int h = 8; h >= 1; h >>= 1) {
#pragma unroll
        for (int base = 0; base < 16; base += 2*h) {
#pragma unroll
            for (int j = 0; j < h; j++) {
                float2 a = r[base+j], b = r[base+j+h];
                r[base+j]   = cadd(a, b);
                r[base+j+h] = cmul(t16[j * (8/h)], csub(a, b));
            }
        }
    }
}

#define FSW(p) ((p) + ((p) >> 3))

// ---------------------------------------------------------------------------
// p1: real 256-pt W-FFT, two-for-one over h pairs. Warp-private smem, no
// block barriers. Writes A[bc][h][w'] rows (129 contiguous float2).
// ---------------------------------------------------------------------------
__global__ void __launch_bounds__(256) p1_kernel(const float* __restrict__ x) {
    __shared__ float2 S[8][289];
    int tid  = threadIdx.x;
    int lane = tid & 31, wp = tid >> 5;
    int bc = blockIdx.x;
    int h0 = blockIdx.y << 4;

    const float* r0 = x + ((size_t)bc * 256 + h0 + 2*wp) * 256;
    const float* r1 = r0 + 256;
    float2 z[8];
#pragma unroll
    for (int i = 0; i < 8; i++) {
        int n = lane + 32*i;
        z[i] = make_float2(r0[n], r1[n]);
    }
    fft256_warp(z, lane);
#pragma unroll
    for (int i = 0; i < 8; i++) {
        int n = lane + 32*i;
        S[wp][FSW(brev8(n))] = z[i];
    }
    __syncwarp();

    float2* outA = g_A + ((size_t)bc * 256 + h0 + 2*wp) * W2;
#pragma unroll
    for (int i = 0; i < 5; i++) {
        int w = lane + 32*i;
        if (w <= 128) {
            float2 Z  = S[wp][FSW(w)];
            float2 Zm = S[wp][FSW((256 - w) & 255)];
            float2 Xe = make_float2(0.5f*(Z.x + Zm.x), 0.5f*(Z.y - Zm.y));
            float2 Xo = make_float2(0.5f*(Z.y + Zm.y), 0.5f*(Zm.x - Z.x));
            outA[w]      = Xe;
            outA[W2 + w] = Xo;
        }
    }
}

// ---------------------------------------------------------------------------
// p2: 256-pt H-FFT. Block = (bc, 16-w'-chunk). Tile S[w][h], warp per column.
// Writes B[hs][bc][w'] with hs = stored (bit-reversed) h.
// ---------------------------------------------------------------------------
__global__ void __launch_bounds__(128) p2_kernel() {
    __shared__ float2 S[16][257];
    int tid = threadIdx.x;
    int bc = blockIdx.x;
    int w0 = blockIdx.y << 4;
    int lw = tid & 15;
    int hq = tid >> 4;            // 0..7

    const float2* src = g_A + (size_t)bc * 256 * W2 + w0;
#pragma unroll
    for (int j = 0; j < 32; j++) {
        int h = hq + 8*j;
        S[lw][h] = src[(size_t)h * W2 + lw];
    }
    __syncthreads();

    int lane = tid & 31, wid = tid >> 5;
#pragma unroll
    for (int it = 0; it < 4; it++) {
        int col = wid + 4*it;
        float2 z[8];
#pragma unroll
        for (int i = 0; i < 8; i++) z[i] = S[col][lane + 32*i];
        fft256_warp(z, lane);
#pragma unroll
        for (int i = 0; i < 8; i++) S[col][lane + 32*i] = z[i];
    }
    __syncthreads();

    float2* dst = g_B + w0;
#pragma unroll
    for (int j = 0; j < 32; j++) {
        int hs = hq + 8*j;
        dst[((size_t)hs * 1024 + bc) * W2 + lw] = S[lw][hs];
    }
}

// p2e: H-FFT for the w'=128 column only. 4 warps/block, warp per bc.
__global__ void __launch_bounds__(128) p2e_kernel() {
    int lane = threadIdx.x & 31, wp = threadIdx.x >> 5;
    int bc = blockIdx.x * 4 + wp;
    const float2* src = g_A + (size_t)bc * 256 * W2 + 128;
    float2 z[8];
#pragma unroll
    for (int i = 0; i < 8; i++) z[i] = src[(size_t)(lane + 32*i) * W2];
    fft256_warp(z, lane);
#pragma unroll
    for (int i = 0; i < 8; i++)
        g_B[((size_t)(lane + 32*i) * 1024 + bc) * W2 + 128] = z[i];
}

// ---------------------------------------------------------------------------
// p3: FUSED (B,C)-FFT + output, w' 0..127. Block = (stored h, 16-w'-chunk).
// Smem tile S[1024 bc][17] (139 KB dynamic). Phase A: 16-pt b-FFT in regs
// from global. Phase B: 64-pt c-FFT via warp shuffles, warp-private rows.
// Phase C: coalesced direct + Hermitian-mirror output writes.
// ---------------------------------------------------------------------------
#define SR 17
__global__ void __launch_bounds__(512) p3_kernel(float* __restrict__ out) {
    extern __shared__ float2 S[];   // [1024][SR]
    int tid = threadIdx.x;
    int ch = blockIdx.x & 7;
    int hs = blockIdx.x >> 3;
    int w0 = ch << 4;
    int w  = tid & 15;
    int c0 = tid >> 4;              // 0..31

    float2 t16[8];
#pragma unroll
    for (int e = 0; e < 8; e++) t16[e] = Wang((float)e, 0.125f);

    // Phase A: 16-pt b-FFT straight from global (coalesced reads).
    const float2* Bb = g_B + (size_t)hs * 1024 * W2 + w0 + w;
#pragma unroll
    for (int j = 0; j < 2; j++) {
        int c = c0 + 32*j;
        float2 r[16];
#pragma unroll
        for (int b = 0; b < 16; b++) r[b] = Bb[(size_t)(b*64 + c) * W2];
        dif16(r, t16);
#pragma unroll
        for (int p = 0; p < 16; p++) S[(p*64 + c)*SR + w] = r[p];
    }
    __syncthreads();

    // Phase B: 64-pt c-FFT; warp p owns rows [p*64, p*64+64) exclusively.
    int lane = tid & 31;
    int p = tid >> 5;               // 16 warps = 16 p
    const float sc = 1.0f / 32.0f;
#pragma unroll
    for (int wg = 0; wg < 4; wg++) {
        float2 z0[4], z1[4];
#pragma unroll
        for (int k = 0; k < 4; k++) {
            z0[k] = S[(p*64 + lane)*SR      + wg*4 + k];
            z1[k] = S[(p*64 + lane + 32)*SR + wg*4 + k];
        }
        {   // h = 32 register stage
            float2 tw = Wang((float)lane, sc);
#pragma unroll
            for (int k = 0; k < 4; k++) {
                float2 a = z0[k], b = z1[k];
                z0[k] = cadd(a, b);
                z1[k] = cmul(tw, csub(a, b));
            }
        }
#pragma unroll
        for (int m = 16; m >= 1; m >>= 1) {
            float2 tw = Wang((float)((lane & (m-1)) * (32/m)), sc);
            bool hi = (lane & m) != 0;
#pragma unroll
            for (int k = 0; k < 4; k++) {
                float2 o;
                o.x = __shfl_xor_sync(0xffffffffu, z0[k].x, m);
                o.y = __shfl_xor_sync(0xffffffffu, z0[k].y, m);
                z0[k] = hi ? cmul(tw, csub(o, z0[k])) : cadd(z0[k], o);
                o.x = __shfl_xor_sync(0xffffffffu, z1[k].x, m);
                o.y = __shfl_xor_sync(0xffffffffu, z1[k].y, m);
                z1[k] = hi ? cmul(tw, csub(o, z1[k])) : cadd(z1[k], o);
            }
        }
#pragma unroll
        for (int k = 0; k < 4; k++) {
            S[(p*64 + lane)*SR      + wg*4 + k] = z0[k];
            S[(p*64 + lane + 32)*SR + wg*4 + k] = z1[k];
        }
    }
    __syncthreads();

    // Phase C: output. true h = brev8(hs); row (p,cpos) -> true (b,c) by brev.
    int h  = brev8(hs);
    int hm = (256 - h) & 255;
    int wv = w0 + w;
#pragma unroll
    for (int j = 0; j < 32; j++) {
        int row = (tid >> 4) + 32*j;       // 0..1023
        int pp = row >> 6, cc = row & 63;
        int b = brev4(pp), c = brev6(cc);
        float2 v = S[row*SR + w];
        out[((size_t)((b << 6) | c) * 256 + h) * 256 + wv] = (v.x + v.y) * INV_N;
        if (wv >= 1) {
            int bcm = (((16 - b) & 15) << 6) | ((64 - c) & 63);
            out[((size_t)bcm * 256 + hm) * 256 + (256 - wv)] = (v.x - v.y) * INV_N;
        }
    }
}

// p3e: (B,C)-FFT + output for the w'=128 plane (self-mirror column).
__global__ void __launch_bounds__(128) p3e_kernel(float* __restrict__ out) {
    __shared__ float2 S[1024];
    int tid = threadIdx.x;
    int hs = blockIdx.x;

    for (int idx = tid; idx < 1024; idx += 128)
        S[idx] = g_B[((size_t)hs * 1024 + idx) * W2 + 128];
    __syncthreads();

    if (tid < 64) {
        float2 t16[8];
#pragma unroll
        for (int e = 0; e < 8; e++) t16[e] = Wang((float)e, 0.125f);
        float2 r[16];
#pragma unroll
        for (int b = 0; b < 16; b++) r[b] = S[b*64 + tid];
        dif16(r, t16);
#pragma unroll
        for (int p = 0; p < 16; p++) S[p*64 + tid] = r[p];
    }
    __syncthreads();

    int lane = tid & 31;
    int h = brev8(hs);
    const float sc = 1.0f / 32.0f;
#pragma unroll
    for (int it = 0; it < 4; it++) {
        int p = (tid >> 5) + 4*it;
        float2 z0 = S[p*64 + lane];
        float2 z1 = S[p*64 + lane + 32];
        {
            float2 tw = Wang((float)lane, sc);
            float2 a = z0, b = z1;
            z0 = cadd(a, b);
            z1 = cmul(tw, csub(a, b));
        }
#pragma unroll
        for (int m = 16; m >= 1; m >>= 1) {
            float2 tw = Wang((float)((lane & (m-1)) * (32/m)), sc);
            bool hi = (lane & m) != 0;
            float2 o;
            o.x = __shfl_xor_sync(0xffffffffu, z0.x, m);
            o.y = __shfl_xor_sync(0xffffffffu, z0.y, m);
            z0 = hi ? cmul(tw, csub(o, z0)) : cadd(z0, o);
            o.x = __shfl_xor_sync(0xffffffffu, z1.x, m);
            o.y = __shfl_xor_sync(0xffffffffu, z1.y, m);
            z1 = hi ? cmul(tw, csub(o, z1)) : cadd(z1, o);
        }
        int b = brev4(p);
        int c0t = brev6(lane);
        int c1t = brev6(lane + 32);
        out[((size_t)((b << 6) | c0t) * 256 + h) * 256 + 128] = (z0.x + z0.y) * INV_N;
        out[((size_t)((b << 6) | c1t) * 256 + h) * 256 + 128] = (z1.x + z1.y) * INV_N;
    }
}

// ---------------------------------------------------------------------------
extern "C" void kernel_launch(void* const* d_in, const int* in_sizes, int n_in,
                              void* d_out, int out_size) {
    (void)in_sizes; (void)n_in; (void)out_size;
    const float* x = (const float*)d_in[0];
    float* out = (float*)d_out;

    static int smem_set = 0;
    if (!smem_set) {
        cudaFuncSetAttribute(p3_kernel,
                             cudaFuncAttributeMaxDynamicSharedMemorySize,
                             1024 * SR * (int)sizeof(float2));
        smem_set = 1;
    }

    p1_kernel<<<dim3(1024, 16), 256>>>(x);
    p2_kernel<<<dim3(1024, 8), 128>>>();
    p2e_kernel<<<256, 128>>>();
    p3_kernel<<<2048, 512, 1024 * SR * sizeof(float2)>>>(out);
    p3e_kernel<<<256, 128>>>(out);
}

// round 5
// speedup vs baseline: 2.6908x; 1.0807x over previous
#include <cuda_runtime.h>

// out[b,c,h,w] = (Re + Im)( FFT4D(x) ) / 2^26 ; x: [16,64,256,256] f32.
//
// Pipeline (scratch rows padded: W2 = 132 float2 per 129 used):
//  p1 : x -> A[bc][h][w']     (real 256-pt W-FFT, two-for-one, warp-private)
//  p2 : A -> B[hs][bc][w']    (256-pt H-FFT per w' column; hs = brev8(h))
//  p2e: same for w'=128 column
//  p3 : B -> out              (16-pt B-FFT + 64-pt C-FFT + Hermitian mirror
//                              output, fused; w' 0..127)
//  p3e: w'=128 plane -> out column w=128
#define W2 132
__device__ float2 g_A[34603008];   // 1024*256*132
__device__ float2 g_B[34603008];

#define INV_N (1.0f / 67108864.0f)
#define PI_F 3.14159265358979f

__device__ __forceinline__ float2 cmul(float2 a, float2 b) {
    return make_float2(a.x*b.x - a.y*b.y, a.x*b.y + a.y*b.x);
}
__device__ __forceinline__ float2 cadd(float2 a, float2 b) { return make_float2(a.x+b.x, a.y+b.y); }
__device__ __forceinline__ float2 csub(float2 a, float2 b) { return make_float2(a.x-b.x, a.y-b.y); }
// exp(-i*pi*e*sc) via hardware MUFU (fast, ~1e-6 abs err: fine vs 1e-3 gate)
__device__ __forceinline__ float2 Wang(float e, float sc) {
    float2 w; __sincosf(-e * sc * PI_F, &w.y, &w.x); return w;
}
__device__ __forceinline__ int brev4(int v) { return (int)(__brev((unsigned)v) >> 28); }
__device__ __forceinline__ int brev6(int v) { return (int)(__brev((unsigned)v) >> 26); }
__device__ __forceinline__ int brev8(int v) { return (int)(__brev((unsigned)v) >> 24); }

// ---------------------------------------------------------------------------
// Warp-resident 256-pt DIF FFT. Input z[i] = x[lane + 32*i] natural order.
// Output: position n = lane + 32*i holds X[brev8(n)].
// ---------------------------------------------------------------------------
__device__ __forceinline__ void fft256_warp(float2 z[8], int lane) {
    const float sc = 1.0f / 128.0f;
#pragma unroll
    for (int i = 0; i < 4; i++) {                       // h = 128
        float2 a = z[i], b = z[i+4];
        z[i]   = cadd(a, b);
        z[i+4] = cmul(Wang((float)(lane + 32*i), sc), csub(a, b));
    }
    {                                                   // h = 64
        float2 w0 = Wang((float)(2*lane), sc);
        float2 w1 = Wang((float)(2*lane + 64), sc);
        float2 a, b;
        a = z[0]; b = z[2]; z[0] = cadd(a,b); z[2] = cmul(w0, csub(a,b));
        a = z[1]; b = z[3]; z[1] = cadd(a,b); z[3] = cmul(w1, csub(a,b));
        a = z[4]; b = z[6]; z[4] = cadd(a,b); z[6] = cmul(w0, csub(a,b));
        a = z[5]; b = z[7]; z[5] = cadd(a,b); z[7] = cmul(w1, csub(a,b));
    }
    {                                                   // h = 32
        float2 w = Wang((float)(4*lane), sc);
#pragma unroll
        for (int i = 0; i < 8; i += 2) {
            float2 a = z[i], b = z[i+1];
            z[i]   = cadd(a, b);
            z[i+1] = cmul(w, csub(a, b));
        }
    }
#pragma unroll
    for (int m = 16; m >= 1; m >>= 1) {                 // cross-lane stages
        float2 w = Wang((float)((lane & (m-1)) * (128/m)), sc);
        bool hi = (lane & m) != 0;
#pragma unroll
        for (int i = 0; i < 8; i++) {
            float2 o;
            o.x = __shfl_xor_sync(0xffffffffu, z[i].x, m);
            o.y = __shfl_xor_sync(0xffffffffu, z[i].y, m);
            if (hi) z[i] = cmul(w, csub(o, z[i]));
            else    z[i] = cadd(z[i], o);
        }
    }
}

// 16-pt DIF: in/out in r[]; position p holds spectrum index brev4(p).
__device__ __forceinline__ void dif16(float2 r[16], const float2 t16[8]) {
#pragma unroll
    for (int h = 8; h >= 1; h >>= 1) {
#pragma unroll
        for (int base = 0; base < 16; base += 2*h) {
#pragma unroll
            for (int j = 0; j < h; j++) {
                float2 a = r[base+j], b = r[base+j+h];
                r[base+j]   = cadd(a, b);
                r[base+j+h] = cmul(t16[j * (8/h)], csub(a, b));
            }
        }
    }
}

#define FSW(p) ((p) + ((p) >> 3))

// ---------------------------------------------------------------------------
// p1: real 256-pt W-FFT, two-for-one over h pairs. Warp-private smem, no
// block barriers. Writes A[bc][h][w'] rows (129 contiguous float2).
// ---------------------------------------------------------------------------
__global__ void __launch_bounds__(256) p1_kernel(const float* __restrict__ x) {
    __shared__ float2 S[8][289];
    int tid  = threadIdx.x;
    int lane = tid & 31, wp = tid >> 5;
    int bc = blockIdx.x;
    int h0 = blockIdx.y << 4;

    const float* r0 = x + ((size_t)bc * 256 + h0 + 2*wp) * 256;
    const float* r1 = r0 + 256;
    float2 z[8];
#pragma unroll
    for (int i = 0; i < 8; i++) {
        int n = lane + 32*i;
        z[i] = make_float2(r0[n], r1[n]);
    }
    fft256_warp(z, lane);
#pragma unroll
    for (int i = 0; i < 8; i++) {
        int n = lane + 32*i;
        S[wp][FSW(brev8(n))] = z[i];
    }
    __syncwarp();

    float2* outA = g_A + ((size_t)bc * 256 + h0 + 2*wp) * W2;
#pragma unroll
    for (int i = 0; i < 5; i++) {
        int w = lane + 32*i;
        if (w <= 128) {
            float2 Z  = S[wp][FSW(w)];
            float2 Zm = S[wp][FSW((256 - w) & 255)];
            float2 Xe = make_float2(0.5f*(Z.x + Zm.x), 0.5f*(Z.y - Zm.y));
            float2 Xo = make_float2(0.5f*(Z.y + Zm.y), 0.5f*(Zm.x - Z.x));
            outA[w]      = Xe;
            outA[W2 + w] = Xo;
        }
    }
}

// ---------------------------------------------------------------------------
// p2: 256-pt H-FFT. Block = (bc, 16-w'-chunk). Tile S[w][h], warp per column.
// Writes B[hs][bc][w'] with hs = stored (bit-reversed) h.
// ---------------------------------------------------------------------------
__global__ void __launch_bounds__(128) p2_kernel() {
    __shared__ float2 S[16][257];
    int tid = threadIdx.x;
    int bc = blockIdx.x;
    int w0 = blockIdx.y << 4;
    int lw = tid & 15;
    int hq = tid >> 4;            // 0..7

    const float2* src = g_A + (size_t)bc * 256 * W2 + w0;
#pragma unroll
    for (int j = 0; j < 32; j++) {
        int h = hq + 8*j;
        S[lw][h] = src[(size_t)h * W2 + lw];
    }
    __syncthreads();

    int lane = tid & 31, wid = tid >> 5;
#pragma unroll
    for (int it = 0; it < 4; it++) {
        int col = wid + 4*it;
        float2 z[8];
#pragma unroll
        for (int i = 0; i < 8; i++) z[i] = S[col][lane + 32*i];
        fft256_warp(z, lane);
#pragma unroll
        for (int i = 0; i < 8; i++) S[col][lane + 32*i] = z[i];
    }
    __syncthreads();

    float2* dst = g_B + w0;
#pragma unroll
    for (int j = 0; j < 32; j++) {
        int hs = hq + 8*j;
        dst[((size_t)hs * 1024 + bc) * W2 + lw] = S[lw][hs];
    }
}

// p2e: H-FFT for the w'=128 column only. 4 warps/block, warp per bc.
__global__ void __launch_bounds__(128) p2e_kernel() {
    int lane = threadIdx.x & 31, wp = threadIdx.x >> 5;
    int bc = blockIdx.x * 4 + wp;
    const float2* src = g_A + (size_t)bc * 256 * W2 + 128;
    float2 z[8];
#pragma unroll
    for (int i = 0; i < 8; i++) z[i] = src[(size_t)(lane + 32*i) * W2];
    fft256_warp(z, lane);
#pragma unroll
    for (int i = 0; i < 8; i++)
        g_B[((size_t)(lane + 32*i) * 1024 + bc) * W2 + 128] = z[i];
}

// ---------------------------------------------------------------------------
// p3: FUSED (B,C)-FFT + output, w' 0..127. Block = (stored h, 16-w'-chunk).
// 1024 threads, 139 KB smem tile S[1024 bc][17] (1 CTA/SM, 32 warps).
// Phase A: 16-pt b-FFT in regs from global (one FFT per thread).
// Phase B: 64-pt c-FFT via warp shuffles; two warps per p, disjoint w-cols.
// Phase C: coalesced direct + Hermitian-mirror output writes.
// ---------------------------------------------------------------------------
#define SR 17
__global__ void __launch_bounds__(1024) p3_kernel(float* __restrict__ out) {
    extern __shared__ float2 S[];   // [1024][SR]
    int tid = threadIdx.x;
    int ch = blockIdx.x & 7;
    int hs = blockIdx.x >> 3;
    int w0 = ch << 4;
    int w  = tid & 15;
    int c  = tid >> 4;              // 0..63

    float2 t16[8];
#pragma unroll
    for (int e = 0; e < 8; e++) t16[e] = Wang((float)e, 0.125f);

    // Phase A: 16-pt b-FFT straight from global (coalesced reads).
    {
        const float2* Bb = g_B + (size_t)hs * 1024 * W2 + w0 + w;
        float2 r[16];
#pragma unroll
        for (int b = 0; b < 16; b++) r[b] = Bb[(size_t)(b*64 + c) * W2];
        dif16(r, t16);
#pragma unroll
        for (int p = 0; p < 16; p++) S[(p*64 + c)*SR + w] = r[p];
    }
    __syncthreads();

    // Phase B: 64-pt c-FFT; warps (2p, 2p+1) share rows p*64.., disjoint cols.
    int lane = tid & 31;
    int wid  = tid >> 5;            // 0..31
    int p    = wid >> 1;
    int wg0  = (wid & 1) * 2;
    const float sc = 1.0f / 32.0f;
    float2 tw32 = Wang((float)lane, sc);
#pragma unroll
    for (int wgi = 0; wgi < 2; wgi++) {
        int wg = wg0 + wgi;
        float2 z0[4], z1[4];
#pragma unroll
        for (int k = 0; k < 4; k++) {
            z0[k] = S[(p*64 + lane)*SR      + wg*4 + k];
            z1[k] = S[(p*64 + lane + 32)*SR + wg*4 + k];
        }
#pragma unroll
        for (int k = 0; k < 4; k++) {   // h = 32 register stage
            float2 a = z0[k], b = z1[k];
            z0[k] = cadd(a, b);
            z1[k] = cmul(tw32, csub(a, b));
        }
#pragma unroll
        for (int m = 16; m >= 1; m >>= 1) {
            float2 tw = Wang((float)((lane & (m-1)) * (32/m)), sc);
            bool hi = (lane & m) != 0;
#pragma unroll
            for (int k = 0; k < 4; k++) {
                float2 o;
                o.x = __shfl_xor_sync(0xffffffffu, z0[k].x, m);
                o.y = __shfl_xor_sync(0xffffffffu, z0[k].y, m);
                z0[k] = hi ? cmul(tw, csub(o, z0[k])) : cadd(z0[k], o);
                o.x = __shfl_xor_sync(0xffffffffu, z1[k].x, m);
                o.y = __shfl_xor_sync(0xffffffffu, z1[k].y, m);
                z1[k] = hi ? cmul(tw, csub(o, z1[k])) : cadd(z1[k], o);
            }
        }
#pragma unroll
        for (int k = 0; k < 4; k++) {
            S[(p*64 + lane)*SR      + wg*4 + k] = z0[k];
            S[(p*64 + lane + 32)*SR + wg*4 + k] = z1[k];
        }
    }
    __syncthreads();

    // Phase C: output. row = c + 64*j -> pp = j, cc = c.
    int h  = brev8(hs);
    int hm = (256 - h) & 255;
    int wv = w0 + w;
    int ct = brev6(c);
#pragma unroll
    for (int j = 0; j < 16; j++) {
        int row = c + 64*j;
        int b = brev4(j);
        float2 v = S[row*SR + w];
        out[((size_t)((b << 6) | ct) * 256 + h) * 256 + wv] = (v.x + v.y) * INV_N;
        if (wv >= 1) {
            int bcm = (((16 - b) & 15) << 6) | ((64 - ct) & 63);
            out[((size_t)bcm * 256 + hm) * 256 + (256 - wv)] = (v.x - v.y) * INV_N;
        }
    }
}

// p3e: (B,C)-FFT + output for the w'=128 plane (self-mirror column).
__global__ void __launch_bounds__(128) p3e_kernel(float* __restrict__ out) {
    __shared__ float2 S[1024];
    int tid = threadIdx.x;
    int hs = blockIdx.x;

    for (int idx = tid; idx < 1024; idx += 128)
        S[idx] = g_B[((size_t)hs * 1024 + idx) * W2 + 128];
    __syncthreads();

    if (tid < 64) {
        float2 t16[8];
#pragma unroll
        for (int e = 0; e < 8; e++) t16[e] = Wang((float)e, 0.125f);
        float2 r[16];
#pragma unroll
        for (int b = 0; b < 16; b++) r[b] = S[b*64 + tid];
        dif16(r, t16);
#pragma unroll
        for (int p = 0; p < 16; p++) S[p*64 + tid] = r[p];
    }
    __syncthreads();

    int lane = tid & 31;
    int h = brev8(hs);
    const float sc = 1.0f / 32.0f;
#pragma unroll
    for (int it = 0; it < 4; it++) {
        int p = (tid >> 5) + 4*it;
        float2 z0 = S[p*64 + lane];
        float2 z1 = S[p*64 + lane + 32];
        {
            float2 tw = Wang((float)lane, sc);
            float2 a = z0, b = z1;
            z0 = cadd(a, b);
            z1 = cmul(tw, csub(a, b));
        }
#pragma unroll
        for (int m = 16; m >= 1; m >>= 1) {
            float2 tw = Wang((float)((lane & (m-1)) * (32/m)), sc);
            bool hi = (lane & m) != 0;
            float2 o;
            o.x = __shfl_xor_sync(0xffffffffu, z0.x, m);
            o.y = __shfl_xor_sync(0xffffffffu, z0.y, m);
            z0 = hi ? cmul(tw, csub(o, z0)) : cadd(z0, o);
            o.x = __shfl_xor_sync(0xffffffffu, z1.x, m);
            o.y = __shfl_xor_sync(0xffffffffu, z1.y, m);
            z1 = hi ? cmul(tw, csub(o, z1)) : cadd(z1, o);
        }
        int b = brev4(p);
        int c0t = brev6(lane);
        int c1t = brev6(lane + 32);
        out[((size_t)((b << 6) | c0t) * 256 + h) * 256 + 128] = (z0.x + z0.y) * INV_N;
        out[((size_t)((b << 6) | c1t) * 256 + h) * 256 + 128] = (z1.x + z1.y) * INV_N;
    }
}

// ---------------------------------------------------------------------------
extern "C" void kernel_launch(void* const* d_in, const int* in_sizes, int n_in,
                              void* d_out, int out_size) {
    (void)in_sizes; (void)n_in; (void)out_size;
    const float* x = (const float*)d_in[0];
    float* out = (float*)d_out;

    static int smem_set = 0;
    if (!smem_set) {
        cudaFuncSetAttribute(p3_kernel,
                             cudaFuncAttributeMaxDynamicSharedMemorySize,
                             1024 * SR * (int)sizeof(float2));
        smem_set = 1;
    }

    p1_kernel<<<dim3(1024, 16), 256>>>(x);
    p2_kernel<<<dim3(1024, 8), 128>>>();
    p2e_kernel<<<256, 128>>>();
    p3_kernel<<<2048, 1024, 1024 * SR * sizeof(float2)>>>(out);
    p3e_kernel<<<256, 128>>>(out);
}

// round 6
// speedup vs baseline: 3.3495x; 1.2448x over previous
#include <cuda_runtime.h>
#include <cuda_fp16.h>

// out[b,c,h,w] = (Re + Im)( FFT4D(x) ) / 2^26 ; x: [16,64,256,256] f32.
//
// Pipeline (scratch = packed half2 complex, rows padded to W2 = 132):
//  p1 : x -> A[bc][h][w']     (real 256-pt W-FFT, two-for-one, warp-private)
//  p2 : A -> B[hs][bc][w']    (256-pt H-FFT per w' column; hs = brev8(h))
//  p2e: same for w'=128 column
//  p3 : B -> out              (16-pt B-FFT + 64-pt C-FFT + Hermitian mirror
//                              output, fused; w' 0..127; 8-w' tiles, 2 CTA/SM)
//  p3e: w'=128 plane -> out column w=128
#define W2 132
__device__ unsigned int g_A[34603008];   // 1024*256*132 half2
__device__ unsigned int g_B[34603008];

#define INV_N (1.0f / 67108864.0f)
#define PI_F 3.14159265358979f

__device__ __forceinline__ float2 cmul(float2 a, float2 b) {
    return make_float2(a.x*b.x - a.y*b.y, a.x*b.y + a.y*b.x);
}
__device__ __forceinline__ float2 cadd(float2 a, float2 b) { return make_float2(a.x+b.x, a.y+b.y); }
__device__ __forceinline__ float2 csub(float2 a, float2 b) { return make_float2(a.x-b.x, a.y-b.y); }
__device__ __forceinline__ float2 Wang(float e, float sc) {   // exp(-i*pi*e*sc), MUFU
    float2 w; __sincosf(-e * sc * PI_F, &w.y, &w.x); return w;
}
__device__ __forceinline__ unsigned int pk(float2 v) {
    __half2 h = __floats2half2_rn(v.x, v.y);
    return *reinterpret_cast<unsigned int*>(&h);
}
__device__ __forceinline__ float2 upk(unsigned int u) {
    __half2 h = *reinterpret_cast<__half2*>(&u);
    return __half22float2(h);
}
__device__ __forceinline__ int brev4(int v) { return (int)(__brev((unsigned)v) >> 28); }
__device__ __forceinline__ int brev6(int v) { return (int)(__brev((unsigned)v) >> 26); }
__device__ __forceinline__ int brev8(int v) { return (int)(__brev((unsigned)v) >> 24); }

// W16^e, e = 0..7 (compile-time constants)
__device__ __constant__ float2 T16C[8] = {
    { 1.00000000f,  0.00000000f}, { 0.92387953f, -0.38268343f},
    { 0.70710678f, -0.70710678f}, { 0.38268343f, -0.92387953f},
    { 0.00000000f, -1.00000000f}, {-0.38268343f, -0.92387953f},
    {-0.70710678f, -0.70710678f}, {-0.92387953f, -0.38268343f}};

// ---------------------------------------------------------------------------
// Warp-resident 256-pt DIF FFT. Input z[i] = x[lane + 32*i] natural order.
// Output: position n = lane + 32*i holds X[brev8(n)].
// ---------------------------------------------------------------------------
__device__ __forceinline__ void fft256_warp(float2 z[8], int lane) {
    const float sc = 1.0f / 128.0f;
#pragma unroll
    for (int i = 0; i < 4; i++) {                       // h = 128
        float2 a = z[i], b = z[i+4];
        z[i]   = cadd(a, b);
        z[i+4] = cmul(Wang((float)(lane + 32*i), sc), csub(a, b));
    }
    {                                                   // h = 64
        float2 w0 = Wang((float)(2*lane), sc);
        float2 w1 = Wang((float)(2*lane + 64), sc);
        float2 a, b;
        a = z[0]; b = z[2]; z[0] = cadd(a,b); z[2] = cmul(w0, csub(a,b));
        a = z[1]; b = z[3]; z[1] = cadd(a,b); z[3] = cmul(w1, csub(a,b));
        a = z[4]; b = z[6]; z[4] = cadd(a,b); z[6] = cmul(w0, csub(a,b));
        a = z[5]; b = z[7]; z[5] = cadd(a,b); z[7] = cmul(w1, csub(a,b));
    }
    {                                                   // h = 32
        float2 w = Wang((float)(4*lane), sc);
#pragma unroll
        for (int i = 0; i < 8; i += 2) {
            float2 a = z[i], b = z[i+1];
            z[i]   = cadd(a, b);
            z[i+1] = cmul(w, csub(a, b));
        }
    }
#pragma unroll
    for (int m = 16; m >= 1; m >>= 1) {                 // cross-lane stages
        float2 w = Wang((float)((lane & (m-1)) * (128/m)), sc);
        bool hi = (lane & m) != 0;
#pragma unroll
        for (int i = 0; i < 8; i++) {
            float2 o;
            o.x = __shfl_xor_sync(0xffffffffu, z[i].x, m);
            o.y = __shfl_xor_sync(0xffffffffu, z[i].y, m);
            if (hi) z[i] = cmul(w, csub(o, z[i]));
            else    z[i] = cadd(z[i], o);
        }
    }
}

// 16-pt DIF; position p holds spectrum index brev4(p).
__device__ __forceinline__ void dif16(float2 r[16]) {
#pragma unroll
    for (int h = 8; h >= 1; h >>= 1) {
#pragma unroll
        for (int base = 0; base < 16; base += 2*h) {
#pragma unroll
            for (int j = 0; j < h; j++) {
                float2 a = r[base+j], b = r[base+j+h];
                r[base+j]   = cadd(a, b);
                r[base+j+h] = cmul(T16C[j * (8/h)], csub(a, b));
            }
        }
    }
}

#define FSW(p) ((p) + ((p) >> 3))

// ---------------------------------------------------------------------------
// p1: real 256-pt W-FFT, two-for-one over h pairs. Warp-private, no block
// barriers. Writes A[bc][h][w'] rows (129 used half2, W2-padded).
// ---------------------------------------------------------------------------
__global__ void __launch_bounds__(256) p1_kernel(const float* __restrict__ x) {
    __shared__ float2 S[8][289];
    int tid  = threadIdx.x;
    int lane = tid & 31, wp = tid >> 5;
    int bc = blockIdx.x;
    int h0 = blockIdx.y << 4;

    const float* r0 = x + ((size_t)bc * 256 + h0 + 2*wp) * 256;
    const float* r1 = r0 + 256;
    float2 z[8];
#pragma unroll
    for (int i = 0; i < 8; i++) {
        int n = lane + 32*i;
        z[i] = make_float2(r0[n], r1[n]);
    }
    fft256_warp(z, lane);
#pragma unroll
    for (int i = 0; i < 8; i++) {
        int n = lane + 32*i;
        S[wp][FSW(brev8(n))] = z[i];
    }
    __syncwarp();

    unsigned int* outA = g_A + ((size_t)bc * 256 + h0 + 2*wp) * W2;
#pragma unroll
    for (int i = 0; i < 5; i++) {
        int w = lane + 32*i;
        if (w <= 128) {
            float2 Z  = S[wp][FSW(w)];
            float2 Zm = S[wp][FSW((256 - w) & 255)];
            float2 Xe = make_float2(0.5f*(Z.x + Zm.x), 0.5f*(Z.y - Zm.y));
            float2 Xo = make_float2(0.5f*(Z.y + Zm.y), 0.5f*(Zm.x - Z.x));
            outA[w]      = pk(Xe);
            outA[W2 + w] = pk(Xo);
        }
    }
}

// ---------------------------------------------------------------------------
// p2: 256-pt H-FFT. Block = (bc, 16-w'-chunk), 256 threads. Tile S[w][h],
// warp per column. Writes B[hs][bc][w'] with hs = bit-reversed h.
// ---------------------------------------------------------------------------
__global__ void __launch_bounds__(256) p2_kernel() {
    __shared__ float2 S[16][257];
    int tid = threadIdx.x;
    int bc = blockIdx.x;
    int w0 = blockIdx.y << 4;
    int lw = tid & 15;
    int hq = tid >> 4;            // 0..15

    const unsigned int* src = g_A + (size_t)bc * 256 * W2 + w0;
#pragma unroll
    for (int j = 0; j < 16; j++) {
        int h = hq + 16*j;
        S[lw][h] = upk(src[(size_t)h * W2 + lw]);
    }
    __syncthreads();

    int lane = tid & 31, wid = tid >> 5;
#pragma unroll
    for (int it = 0; it < 2; it++) {
        int col = wid + 8*it;
        float2 z[8];
#pragma unroll
        for (int i = 0; i < 8; i++) z[i] = S[col][lane + 32*i];
        fft256_warp(z, lane);
#pragma unroll
        for (int i = 0; i < 8; i++) S[col][lane + 32*i] = z[i];
    }
    __syncthreads();

    unsigned int* dst = g_B + w0;
#pragma unroll
    for (int j = 0; j < 16; j++) {
        int hs = hq + 16*j;
        dst[((size_t)hs * 1024 + bc) * W2 + lw] = pk(S[lw][hs]);
    }
}

// p2e: H-FFT for the w'=128 column only. 4 warps/block, warp per bc.
__global__ void __launch_bounds__(128) p2e_kernel() {
    int lane = threadIdx.x & 31, wp = threadIdx.x >> 5;
    int bc = blockIdx.x * 4 + wp;
    const unsigned int* src = g_A + (size_t)bc * 256 * W2 + 128;
    float2 z[8];
#pragma unroll
    for (int i = 0; i < 8; i++) z[i] = upk(src[(size_t)(lane + 32*i) * W2]);
    fft256_warp(z, lane);
#pragma unroll
    for (int i = 0; i < 8; i++)
        g_B[((size_t)(lane + 32*i) * 1024 + bc) * W2 + 128] = pk(z[i]);
}

// ---------------------------------------------------------------------------
// p3: FUSED (B,C)-FFT + output, w' 0..127. Block = (stored h, 8-w'-chunk).
// 512 threads, 74 KB smem tile S[1024 bc][9] -> 2 CTAs/SM.
// Phase A: 16-pt b-FFT in regs from global (one FFT per thread).
// Phase B: 64-pt c-FFT via warp shuffles; warp p owns rows p*64.., 8 w-cols.
// Phase C: coalesced direct + Hermitian-mirror output writes.
// ---------------------------------------------------------------------------
#define SR 9
__global__ void __launch_bounds__(512) p3_kernel(float* __restrict__ out) {
    extern __shared__ float2 S[];   // [1024][SR]
    int tid = threadIdx.x;
    int ch = blockIdx.x & 15;
    int hs = blockIdx.x >> 4;
    int w0 = ch << 3;
    int w  = tid & 7;
    int c  = tid >> 3;              // 0..63

    // Phase A: 16-pt b-FFT straight from global (coalesced reads).
    {
        const unsigned int* Bb = g_B + (size_t)hs * 1024 * W2 + w0 + w;
        float2 r[16];
#pragma unroll
        for (int b = 0; b < 16; b++) r[b] = upk(Bb[(size_t)(b*64 + c) * W2]);
        dif16(r);
#pragma unroll
        for (int p = 0; p < 16; p++) S[(p*64 + c)*SR + w] = r[p];
    }
    __syncthreads();

    // Phase B: 64-pt c-FFT; warp p owns rows [p*64, p*64+64), cols w0..w0+7.
    int lane = tid & 31;
    int p    = tid >> 5;            // 0..15
    const float sc = 1.0f / 32.0f;
    float2 tw32 = Wang((float)lane, sc);
#pragma unroll
    for (int wg = 0; wg < 2; wg++) {
        float2 z0[4], z1[4];
#pragma unroll
        for (int k = 0; k < 4; k++) {
            z0[k] = S[(p*64 + lane)*SR      + wg*4 + k];
            z1[k] = S[(p*64 + lane + 32)*SR + wg*4 + k];
        }
#pragma unroll
        for (int k = 0; k < 4; k++) {   // h = 32 register stage
            float2 a = z0[k], b = z1[k];
            z0[k] = cadd(a, b);
            z1[k] = cmul(tw32, csub(a, b));
        }
#pragma unroll
        for (int m = 16; m >= 1; m >>= 1) {
            float2 tw = Wang((float)((lane & (m-1)) * (32/m)), sc);
            bool hi = (lane & m) != 0;
#pragma unroll
            for (int k = 0; k < 4; k++) {
                float2 o;
                o.x = __shfl_xor_sync(0xffffffffu, z0[k].x, m);
                o.y = __shfl_xor_sync(0xffffffffu, z0[k].y, m);
                z0[k] = hi ? cmul(tw, csub(o, z0[k])) : cadd(z0[k], o);
                o.x = __shfl_xor_sync(0xffffffffu, z1[k].x, m);
                o.y = __shfl_xor_sync(0xffffffffu, z1[k].y, m);
                z1[k] = hi ? cmul(tw, csub(o, z1[k])) : cadd(z1[k], o);
            }
        }
#pragma unroll
        for (int k = 0; k < 4; k++) {
            S[(p*64 + lane)*SR      + wg*4 + k] = z0[k];
            S[(p*64 + lane + 32)*SR + wg*4 + k] = z1[k];
        }
    }
    __syncthreads();

    // Phase C: output. row = c + 64*j -> b = brev4(j), true c = brev6(c).
    int h  = brev8(hs);
    int hm = (256 - h) & 255;
    int wv = w0 + w;
    int ct = brev6(c);
#pragma unroll
    for (int j = 0; j < 16; j++) {
        int row = c + 64*j;
        int b = brev4(j);
        float2 v = S[row*SR + w];
        out[((size_t)((b << 6) | ct) * 256 + h) * 256 + wv] = (v.x + v.y) * INV_N;
        if (wv >= 1) {
            int bcm = (((16 - b) & 15) << 6) | ((64 - ct) & 63);
            out[((size_t)bcm * 256 + hm) * 256 + (256 - wv)] = (v.x - v.y) * INV_N;
        }
    }
}

// p3e: (B,C)-FFT + output for the w'=128 plane (self-mirror column).
__global__ void __launch_bounds__(128) p3e_kernel(float* __restrict__ out) {
    __shared__ float2 S[1024];
    int tid = threadIdx.x;
    int hs = blockIdx.x;

    for (int idx = tid; idx < 1024; idx += 128)
        S[idx] = upk(g_B[((size_t)hs * 1024 + idx) * W2 + 128]);
    __syncthreads();

    if (tid < 64) {
        float2 r[16];
#pragma unroll
        for (int b = 0; b < 16; b++) r[b] = S[b*64 + tid];
        dif16(r);
#pragma unroll
        for (int p = 0; p < 16; p++) S[p*64 + tid] = r[p];
    }
    __syncthreads();

    int lane = tid & 31;
    int h = brev8(hs);
    const float sc = 1.0f / 32.0f;
#pragma unroll
    for (int it = 0; it < 4; it++) {
        int p = (tid >> 5) + 4*it;
        float2 z0 = S[p*64 + lane];
        float2 z1 = S[p*64 + lane + 32];
        {
            float2 tw = Wang((float)lane, sc);
            float2 a = z0, b = z1;
            z0 = cadd(a, b);
            z1 = cmul(tw, csub(a, b));
        }
#pragma unroll
        for (int m = 16; m >= 1; m >>= 1) {
            float2 tw = Wang((float)((lane & (m-1)) * (32/m)), sc);
            bool hi = (lane & m) != 0;
            float2 o;
            o.x = __shfl_xor_sync(0xffffffffu, z0.x, m);
            o.y = __shfl_xor_sync(0xffffffffu, z0.y, m);
            z0 = hi ? cmul(tw, csub(o, z0)) : cadd(z0, o);
            o.x = __shfl_xor_sync(0xffffffffu, z1.x, m);
            o.y = __shfl_xor_sync(0xffffffffu, z1.y, m);
            z1 = hi ? cmul(tw, csub(o, z1)) : cadd(z1, o);
        }
        int b = brev4(p);
        int c0t = brev6(lane);
        int c1t = brev6(lane + 32);
        out[((size_t)((b << 6) | c0t) * 256 + h) * 256 + 128] = (z0.x + z0.y) * INV_N;
        out[((size_t)((b << 6) | c1t) * 256 + h) * 256 + 128] = (z1.x + z1.y) * INV_N;
    }
}

// ---------------------------------------------------------------------------
extern "C" void kernel_launch(void* const* d_in, const int* in_sizes, int n_in,
                              void* d_out, int out_size) {
    (void)in_sizes; (void)n_in; (void)out_size;
    const float* x = (const float*)d_in[0];
    float* out = (float*)d_out;

    static int smem_set = 0;
    if (!smem_set) {
        cudaFuncSetAttribute(p3_kernel,
                             cudaFuncAttributeMaxDynamicSharedMemorySize,
                             1024 * SR * (int)sizeof(float2));
        smem_set = 1;
    }

    p1_kernel<<<dim3(1024, 16), 256>>>(x);
    p2_kernel<<<dim3(1024, 8), 256>>>();
    p2e_kernel<<<256, 128>>>();
    p3_kernel<<<4096, 512, 1024 * SR * sizeof(float2)>>>(out);
    p3e_kernel<<<256, 128>>>(out);
}